// round 8
// baseline (speedup 1.0000x reference)
#include <cuda_runtime.h>
#include <cstdint>

#define B_SZ   256
#define F_SZ   128
#define DEPTHD 6
#define C_SZ   100
#define L_SZ   64
#define NTREE  8192
#define KTOT   ((size_t)NTREE * L_SZ)     /* 524288 */
#define NSLICE 148                        /* one CTA per tree-slice */
#define N_PAD  104                        /* C padded: 13 n-tiles of 8 */
#define SST    68                         /* sel smem stride (words), 68 mod 32 = 4 */
#define HST    36                         /* accum smem stride (words), 36 mod 32 = 4 */
#define W_SCALE   512.0f
#define W_INV     0.001953125f            /* 1/512 */

/* scratch: fv[m = tree*6+d][b], 49152 x 256 floats = 50.3 MB */
__device__ float g_fv[NTREE * DEPTHD * B_SZ];

/* ---- helpers ---- */
/* pack (lo, hi) floats -> f16x2 reg. PTX: cvt d, a, b => d.lo = b, d.hi = a */
__device__ __forceinline__ uint32_t f2h2(float lo, float hi) {
    uint32_t u; asm("cvt.rn.f16x2.f32 %0, %1, %2;" : "=r"(u) : "f"(hi), "f"(lo)); return u;
}
__device__ __forceinline__ void mma16(float c[4],
                                      uint32_t a0, uint32_t a1, uint32_t a2, uint32_t a3,
                                      uint32_t b0, uint32_t b1) {
    asm volatile(
        "mma.sync.aligned.m16n8k16.row.col.f32.f16.f16.f32 "
        "{%0,%1,%2,%3}, {%4,%5,%6,%7}, {%8,%9}, {%0,%1,%2,%3};"
        : "+f"(c[0]), "+f"(c[1]), "+f"(c[2]), "+f"(c[3])
        : "r"(a0), "r"(a1), "r"(a2), "r"(a3), "r"(b0), "r"(b1));
}

/* ================= kernel 1: selector GEMM + sigmoid (fp16 m16n8k16) ========= */
__global__ void __launch_bounds__(256) sel_fp16(const float* __restrict__ x,
                                                const float* __restrict__ selW,
                                                const float* __restrict__ selb) {
    extern __shared__ uint32_t sm[];
    uint32_t* As = sm;                 /* 128 x SST */
    uint32_t* Bs = sm + 128 * SST;     /* 64 x SST  */

    const int tid = threadIdx.x;
    const int wid = tid >> 5, lane = tid & 31;
    const int g = lane >> 2, tg = lane & 3;
    const int mw = wid & 3, nw = wid >> 2;
    const int row0 = blockIdx.x * 128, col0 = blockIdx.y * 64;

#pragma unroll
    for (int it = 0; it < 16; it++) {
        int e = tid + it * 256;
        int r = e >> 5, q = e & 31;
        float4 v = *(const float4*)(selW + (size_t)(row0 + r) * F_SZ + q * 4);
        uint2 w; w.x = f2h2(v.x, v.y); w.y = f2h2(v.z, v.w);
        *(uint2*)&As[r * SST + q * 2] = w;
    }
#pragma unroll
    for (int it = 0; it < 8; it++) {
        int e = tid + it * 256;
        int r = e >> 5, q = e & 31;
        float4 v = *(const float4*)(x + (size_t)(col0 + r) * F_SZ + q * 4);
        uint2 w; w.x = f2h2(v.x, v.y); w.y = f2h2(v.z, v.w);
        *(uint2*)&Bs[r * SST + q * 2] = w;
    }
    __syncthreads();

    float acc[2][4][4];
#pragma unroll
    for (int mi = 0; mi < 2; mi++)
#pragma unroll
        for (int ni = 0; ni < 4; ni++)
#pragma unroll
            for (int q = 0; q < 4; q++) acc[mi][ni][q] = 0.f;

#pragma unroll
    for (int c = 0; c < 8; c++) {
        uint32_t a[2][4], b[4][2];
#pragma unroll
        for (int mi = 0; mi < 2; mi++) {
            int mb = mw * 32 + mi * 16;
            a[mi][0] = As[(mb + g) * SST + 8 * c + tg];
            a[mi][1] = As[(mb + g + 8) * SST + 8 * c + tg];
            a[mi][2] = As[(mb + g) * SST + 8 * c + tg + 4];
            a[mi][3] = As[(mb + g + 8) * SST + 8 * c + tg + 4];
        }
#pragma unroll
        for (int ni = 0; ni < 4; ni++) {
            int nb = nw * 32 + ni * 8 + g;
            b[ni][0] = Bs[nb * SST + 8 * c + tg];
            b[ni][1] = Bs[nb * SST + 8 * c + tg + 4];
        }
#pragma unroll
        for (int mi = 0; mi < 2; mi++)
#pragma unroll
            for (int ni = 0; ni < 4; ni++)
                mma16(acc[mi][ni], a[mi][0], a[mi][1], a[mi][2], a[mi][3],
                      b[ni][0], b[ni][1]);
    }

#pragma unroll
    for (int mi = 0; mi < 2; mi++) {
        int m = row0 + mw * 32 + mi * 16 + g;
        float b0 = selb[m], b1 = selb[m + 8];
#pragma unroll
        for (int ni = 0; ni < 4; ni++) {
            int bcol = col0 + nw * 32 + ni * 8 + tg * 2;
            float2 v0, v1;
            v0.x = 1.f / (1.f + __expf(-(acc[mi][ni][0] + b0)));
            v0.y = 1.f / (1.f + __expf(-(acc[mi][ni][1] + b0)));
            v1.x = 1.f / (1.f + __expf(-(acc[mi][ni][2] + b1)));
            v1.y = 1.f / (1.f + __expf(-(acc[mi][ni][3] + b1)));
            *(float2*)&g_fv[(size_t)m * B_SZ + bcol] = v0;
            *(float2*)&g_fv[(size_t)(m + 8) * B_SZ + bcol] = v1;
        }
    }
}

/* ================= kernel 2: fused leaf + fp16 GEMM, 768 thr =================
 * grid = 148 CTAs, 768 threads (24 warps), 1 CTA/SM, ~85 regs/thread.
 * A = leaf[256 b, 64 l] fp16, B = 512*W[104 c, 64 l] fp16, stride HST=36.
 * 24 warps = 8 mw x 3 n-groups (tiles {5,4,4}); warp = 2 m-tiles x NT n-tiles.
 * Staging: threads 0-511 build leaves (2/row), threads 512-767 stage W. */
__device__ __forceinline__ void stage_768(uint32_t* Ab, uint32_t* Bb, int t,
                                          const float* __restrict__ outW, int tid) {
    if (tid < 512) {
        /* ---- leaf tile: 2 threads per b row; lh = bit5 of l (d0 bit) ---- */
        const int b_local = tid >> 1;
        const int lh = tid & 1;
        const float* fp = g_fv + (size_t)t * (DEPTHD * B_SZ) + b_local;
        float p0 = fp[0], p1 = fp[256], p2 = fp[512];
        float p3 = fp[768], p4 = fp[1024], p5 = fp[1280];
        float g0 = lh ? (1.f - p0) : p0;
        float a1[2], a2[4], a3[8], a4[16];
        a1[0] = g0 * p1; a1[1] = g0 * (1.f - p1);
#pragma unroll
        for (int i = 0; i < 2; i++) { a2[2*i] = a1[i] * p2; a2[2*i+1] = a1[i] * (1.f - p2); }
#pragma unroll
        for (int i = 0; i < 4; i++) { a3[2*i] = a2[i] * p3; a3[2*i+1] = a2[i] * (1.f - p3); }
#pragma unroll
        for (int i = 0; i < 8; i++) { a4[2*i] = a3[i] * p4; a4[2*i+1] = a3[i] * (1.f - p4); }
        float q5 = 1.f - p5;
        uint32_t* dst = Ab + b_local * HST + lh * 16;
#pragma unroll
        for (int i = 0; i < 4; i++) {
            uint4 w;
            w.x = f2h2(a4[4*i]     * p5, a4[4*i]     * q5);
            w.y = f2h2(a4[4*i + 1] * p5, a4[4*i + 1] * q5);
            w.z = f2h2(a4[4*i + 2] * p5, a4[4*i + 2] * q5);
            w.w = f2h2(a4[4*i + 3] * p5, a4[4*i + 3] * q5);
            *(uint4*)(dst + i * 4) = w;
        }
    } else {
        /* ---- W tile: 256 dedicated threads; 104x16 = 1664 float4 ---- */
        const int t2 = tid - 512;
        const float* wp = outW + (size_t)t * L_SZ;
#pragma unroll
        for (int it = 0; it < 7; it++) {
            int e = t2 + it * 256;
            if (e < N_PAD * 16) {
                int c = e >> 4, q = e & 15;
                uint2 w;
                if (c < C_SZ) {
                    float4 v = *(const float4*)(wp + (size_t)c * KTOT + q * 4);
                    w.x = f2h2(v.x * W_SCALE, v.y * W_SCALE);
                    w.y = f2h2(v.z * W_SCALE, v.w * W_SCALE);
                } else {
                    w.x = 0u; w.y = 0u;
                }
                *(uint2*)&Bb[c * HST + q * 2] = w;
            }
        }
    }
}

template <int NT>
__device__ __forceinline__ void mma_768(float acc[2][5][4],
                                        const uint32_t* __restrict__ As,
                                        const uint32_t* __restrict__ Bs,
                                        int mw, int tb, int g, int tg) {
#pragma unroll
    for (int c = 0; c < 4; c++) {
        uint32_t a[2][4], b[NT][2];
#pragma unroll
        for (int mi = 0; mi < 2; mi++) {
            int mb = mw * 32 + mi * 16;
            a[mi][0] = As[(mb + g) * HST + 8 * c + tg];
            a[mi][1] = As[(mb + g + 8) * HST + 8 * c + tg];
            a[mi][2] = As[(mb + g) * HST + 8 * c + tg + 4];
            a[mi][3] = As[(mb + g + 8) * HST + 8 * c + tg + 4];
        }
#pragma unroll
        for (int ni = 0; ni < NT; ni++) {
            int nb = (tb + ni) * 8 + g;
            b[ni][0] = Bs[nb * HST + 8 * c + tg];
            b[ni][1] = Bs[nb * HST + 8 * c + tg + 4];
        }
#pragma unroll
        for (int mi = 0; mi < 2; mi++)
#pragma unroll
            for (int ni = 0; ni < NT; ni++)
                mma16(acc[mi][ni], a[mi][0], a[mi][1], a[mi][2], a[mi][3],
                      b[ni][0], b[ni][1]);
    }
}

__global__ void __launch_bounds__(768, 1) accum_768(const float* __restrict__ outW,
                                                    const float* __restrict__ outb,
                                                    float* __restrict__ out) {
    extern __shared__ uint32_t sm[];
    uint32_t* A0 = sm;                        /* 256*HST words */
    uint32_t* A1 = A0 + 256 * HST;
    uint32_t* B0 = A1 + 256 * HST;            /* 104*HST words */
    uint32_t* B1 = B0 + N_PAD * HST;

    const int tid = threadIdx.x;
    const int wid = tid >> 5, lane = tid & 31;
    const int g = lane >> 2, tg = lane & 3;
    const int mw = wid & 7, nwg = wid >> 3;           /* 8 mw x 3 n-groups */
    const int tb = (nwg == 0) ? 0 : (4 * nwg + 1);    /* first n-tile: 0, 5, 9 */
    const int slice = blockIdx.x;
    const int t0 = (slice * NTREE) / NSLICE;
    const int t1 = ((slice + 1) * NTREE) / NSLICE;

    float acc[2][5][4];
#pragma unroll
    for (int mi = 0; mi < 2; mi++)
#pragma unroll
        for (int ni = 0; ni < 5; ni++)
#pragma unroll
            for (int q = 0; q < 4; q++) acc[mi][ni][q] = 0.f;

    stage_768(A0, B0, t0, outW, tid);
    __syncthreads();

    for (int t = t0; t < t1; t++) {
        const int buf = (t - t0) & 1;
        if (t + 1 < t1)
            stage_768(buf ? A0 : A1, buf ? B0 : B1, t + 1, outW, tid);

        const uint32_t* As = buf ? A1 : A0;
        const uint32_t* Bs = buf ? B1 : B0;
        if (nwg == 0) mma_768<5>(acc, As, Bs, mw, tb, g, tg);
        else          mma_768<4>(acc, As, Bs, mw, tb, g, tg);
        __syncthreads();
    }

    /* epilogue: atomicAdd (undo x512 W scale); CTA 0 also adds the bias */
    const int ntiles = (nwg == 0) ? 5 : 4;
    const bool addb = (blockIdx.x == 0);
#pragma unroll
    for (int mi = 0; mi < 2; mi++) {
        int row = mw * 32 + mi * 16 + g;
        float* op0 = out + (size_t)row * C_SZ;
        float* op1 = out + (size_t)(row + 8) * C_SZ;
#pragma unroll
        for (int ni = 0; ni < 5; ni++) {
            if (ni >= ntiles) break;
            int col = (tb + ni) * 8 + tg * 2;
            if (col < C_SZ) {
                float bb = addb ? outb[col] : 0.f;
                atomicAdd(op0 + col, acc[mi][ni][0] * W_INV + bb);
                atomicAdd(op1 + col, acc[mi][ni][2] * W_INV + bb);
            }
            if (col + 1 < C_SZ) {
                float bb = addb ? outb[col + 1] : 0.f;
                atomicAdd(op0 + col + 1, acc[mi][ni][1] * W_INV + bb);
                atomicAdd(op1 + col + 1, acc[mi][ni][3] * W_INV + bb);
            }
        }
    }
}

extern "C" void kernel_launch(void* const* d_in, const int* in_sizes, int n_in,
                              void* d_out, int out_size) {
    const float* x    = (const float*)d_in[0];
    const float* selW = (const float*)d_in[1];
    const float* selb = (const float*)d_in[2];
    const float* outW = (const float*)d_in[3];
    const float* outb = (const float*)d_in[4];
    float* out = (float*)d_out;

    cudaMemsetAsync(out, 0, (size_t)out_size * sizeof(float));

    size_t sel_smem = (size_t)(128 + 64) * SST * 4;                  /* 52224 B */
    cudaFuncSetAttribute(sel_fp16, cudaFuncAttributeMaxDynamicSharedMemorySize, (int)sel_smem);
    dim3 g1(384, 4);
    sel_fp16<<<g1, 256, sel_smem>>>(x, selW, selb);

    size_t acc_smem = (size_t)(2 * 256 + 2 * N_PAD) * HST * 4;       /* 103680 B */
    cudaFuncSetAttribute(accum_768, cudaFuncAttributeMaxDynamicSharedMemorySize, (int)acc_smem);
    accum_768<<<NSLICE, 768, acc_smem>>>(outW, outb, out);
}

// round 9
// speedup vs baseline: 1.2048x; 1.2048x over previous
#include <cuda_runtime.h>
#include <cstdint>

#define B_SZ   256
#define F_SZ   128
#define DEPTHD 6
#define C_SZ   100
#define L_SZ   64
#define NTREE  8192
#define KTOT   ((size_t)NTREE * L_SZ)     /* 524288 */
#define NSLICE 148                        /* one CTA per tree-slice */
#define N_PAD  104                        /* C padded: 13 n-tiles of 8 */
#define SST    68                         /* sel smem stride (words), 68 mod 32 = 4 */
#define HST    36                         /* accum smem stride (words), 36 mod 32 = 4 */
#define W_SCALE   512.0f
#define W_INV     0.001953125f            /* 1/512 */

/* scratch: fv[m = tree*6+d][b], 49152 x 256 floats = 50.3 MB */
__device__ float g_fv[NTREE * DEPTHD * B_SZ];

/* ---- helpers ---- */
/* pack (lo, hi) floats -> f16x2 reg. PTX: cvt d, a, b => d.lo = b, d.hi = a */
__device__ __forceinline__ uint32_t f2h2(float lo, float hi) {
    uint32_t u; asm("cvt.rn.f16x2.f32 %0, %1, %2;" : "=r"(u) : "f"(hi), "f"(lo)); return u;
}
__device__ __forceinline__ void mma16(float c[4],
                                      uint32_t a0, uint32_t a1, uint32_t a2, uint32_t a3,
                                      uint32_t b0, uint32_t b1) {
    asm volatile(
        "mma.sync.aligned.m16n8k16.row.col.f32.f16.f16.f32 "
        "{%0,%1,%2,%3}, {%4,%5,%6,%7}, {%8,%9}, {%0,%1,%2,%3};"
        : "+f"(c[0]), "+f"(c[1]), "+f"(c[2]), "+f"(c[3])
        : "r"(a0), "r"(a1), "r"(a2), "r"(a3), "r"(b0), "r"(b1));
}

/* ================= kernel 1: selector GEMM + sigmoid (fp16 m16n8k16) ========= */
__global__ void __launch_bounds__(256) sel_fp16(const float* __restrict__ x,
                                                const float* __restrict__ selW,
                                                const float* __restrict__ selb) {
    extern __shared__ uint32_t sm[];
    uint32_t* As = sm;                 /* 128 x SST */
    uint32_t* Bs = sm + 128 * SST;     /* 64 x SST  */

    const int tid = threadIdx.x;
    const int wid = tid >> 5, lane = tid & 31;
    const int g = lane >> 2, tg = lane & 3;
    const int mw = wid & 3, nw = wid >> 2;
    const int row0 = blockIdx.x * 128, col0 = blockIdx.y * 64;

#pragma unroll
    for (int it = 0; it < 16; it++) {
        int e = tid + it * 256;
        int r = e >> 5, q = e & 31;
        float4 v = *(const float4*)(selW + (size_t)(row0 + r) * F_SZ + q * 4);
        uint2 w; w.x = f2h2(v.x, v.y); w.y = f2h2(v.z, v.w);
        *(uint2*)&As[r * SST + q * 2] = w;
    }
#pragma unroll
    for (int it = 0; it < 8; it++) {
        int e = tid + it * 256;
        int r = e >> 5, q = e & 31;
        float4 v = *(const float4*)(x + (size_t)(col0 + r) * F_SZ + q * 4);
        uint2 w; w.x = f2h2(v.x, v.y); w.y = f2h2(v.z, v.w);
        *(uint2*)&Bs[r * SST + q * 2] = w;
    }
    __syncthreads();

    float acc[2][4][4];
#pragma unroll
    for (int mi = 0; mi < 2; mi++)
#pragma unroll
        for (int ni = 0; ni < 4; ni++)
#pragma unroll
            for (int q = 0; q < 4; q++) acc[mi][ni][q] = 0.f;

#pragma unroll
    for (int c = 0; c < 8; c++) {
        uint32_t a[2][4], b[4][2];
#pragma unroll
        for (int mi = 0; mi < 2; mi++) {
            int mb = mw * 32 + mi * 16;
            a[mi][0] = As[(mb + g) * SST + 8 * c + tg];
            a[mi][1] = As[(mb + g + 8) * SST + 8 * c + tg];
            a[mi][2] = As[(mb + g) * SST + 8 * c + tg + 4];
            a[mi][3] = As[(mb + g + 8) * SST + 8 * c + tg + 4];
        }
#pragma unroll
        for (int ni = 0; ni < 4; ni++) {
            int nb = nw * 32 + ni * 8 + g;
            b[ni][0] = Bs[nb * SST + 8 * c + tg];
            b[ni][1] = Bs[nb * SST + 8 * c + tg + 4];
        }
#pragma unroll
        for (int mi = 0; mi < 2; mi++)
#pragma unroll
            for (int ni = 0; ni < 4; ni++)
                mma16(acc[mi][ni], a[mi][0], a[mi][1], a[mi][2], a[mi][3],
                      b[ni][0], b[ni][1]);
    }

#pragma unroll
    for (int mi = 0; mi < 2; mi++) {
        int m = row0 + mw * 32 + mi * 16 + g;
        float b0 = selb[m], b1 = selb[m + 8];
#pragma unroll
        for (int ni = 0; ni < 4; ni++) {
            int bcol = col0 + nw * 32 + ni * 8 + tg * 2;
            float2 v0, v1;
            v0.x = 1.f / (1.f + __expf(-(acc[mi][ni][0] + b0)));
            v0.y = 1.f / (1.f + __expf(-(acc[mi][ni][1] + b0)));
            v1.x = 1.f / (1.f + __expf(-(acc[mi][ni][2] + b1)));
            v1.y = 1.f / (1.f + __expf(-(acc[mi][ni][3] + b1)));
            *(float2*)&g_fv[(size_t)m * B_SZ + bcol] = v0;
            *(float2*)&g_fv[(size_t)(m + 8) * B_SZ + bcol] = v1;
        }
    }
}

/* ================= kernel 2: fused leaf + fp16 GEMM, reg-prefetch pipeline ===
 * grid = 148 CTAs, 512 threads, 1 CTA/SM.
 * Per tree: load_pref issues all LDGs (fv + W) into regs (non-blocking);
 * store_stage converts/stores the PREVIOUS tree's regs; mma overlaps the loads.
 * A = leaf[256 b, 64 l] fp16, B = 512*W[104 c, 64 l] fp16, stride HST=36.
 * 16 warps = 8 mw x 2 nw; warp = 2 m-tiles x {7,6} n-tiles x 4 k-chunks. */
struct Pref {
    float p0, p1, p2, p3, p4, p5;     /* fv for this thread's (b row, lh) */
    float4 w[4];                      /* W slice elements (predicated)     */
};

__device__ __forceinline__ void load_pref(Pref& pr, int t,
                                          const float* __restrict__ outW,
                                          int tid, int b_local) {
    const float* fp = g_fv + (size_t)t * (DEPTHD * B_SZ) + b_local;
    pr.p0 = fp[0];    pr.p1 = fp[256];  pr.p2 = fp[512];
    pr.p3 = fp[768];  pr.p4 = fp[1024]; pr.p5 = fp[1280];
    const float* wp = outW + (size_t)t * L_SZ;
#pragma unroll
    for (int it = 0; it < 4; it++) {
        int e = tid + it * 512;
        int c = e >> 4, q = e & 15;
        if (e < N_PAD * 16 && c < C_SZ)
            pr.w[it] = *(const float4*)(wp + (size_t)c * KTOT + q * 4);
        else
            pr.w[it] = make_float4(0.f, 0.f, 0.f, 0.f);
    }
}

__device__ __forceinline__ void store_stage(const Pref& pr, uint32_t* Ab, uint32_t* Bb,
                                            int tid, int b_local, int lh) {
    /* ---- leaf tile: 2 threads per b row; lh = bit5 of l (d0 bit) ---- */
    {
        float g0 = lh ? (1.f - pr.p0) : pr.p0;
        float a1[2], a2[4], a3[8], a4[16];
        a1[0] = g0 * pr.p1; a1[1] = g0 * (1.f - pr.p1);
#pragma unroll
        for (int i = 0; i < 2; i++) { a2[2*i] = a1[i] * pr.p2; a2[2*i+1] = a1[i] * (1.f - pr.p2); }
#pragma unroll
        for (int i = 0; i < 4; i++) { a3[2*i] = a2[i] * pr.p3; a3[2*i+1] = a2[i] * (1.f - pr.p3); }
#pragma unroll
        for (int i = 0; i < 8; i++) { a4[2*i] = a3[i] * pr.p4; a4[2*i+1] = a3[i] * (1.f - pr.p4); }
        float p5 = pr.p5, q5 = 1.f - pr.p5;
        uint32_t* dst = Ab + b_local * HST + lh * 16;
#pragma unroll
        for (int i = 0; i < 4; i++) {
            uint4 w;
            w.x = f2h2(a4[4*i]     * p5, a4[4*i]     * q5);
            w.y = f2h2(a4[4*i + 1] * p5, a4[4*i + 1] * q5);
            w.z = f2h2(a4[4*i + 2] * p5, a4[4*i + 2] * q5);
            w.w = f2h2(a4[4*i + 3] * p5, a4[4*i + 3] * q5);
            *(uint4*)(dst + i * 4) = w;
        }
    }
    /* ---- W tile ---- */
#pragma unroll
    for (int it = 0; it < 4; it++) {
        int e = tid + it * 512;
        if (e < N_PAD * 16) {
            int c = e >> 4, q = e & 15;
            uint2 w;
            w.x = f2h2(pr.w[it].x * W_SCALE, pr.w[it].y * W_SCALE);
            w.y = f2h2(pr.w[it].z * W_SCALE, pr.w[it].w * W_SCALE);
            *(uint2*)&Bb[c * HST + q * 2] = w;
        }
    }
}

template <int NT>
__device__ __forceinline__ void mma_trees(float acc[2][7][4],
                                          const uint32_t* __restrict__ As,
                                          const uint32_t* __restrict__ Bs,
                                          int mw, int nw, int g, int tg) {
#pragma unroll
    for (int c = 0; c < 4; c++) {
        uint32_t a[2][4], b[NT][2];
#pragma unroll
        for (int mi = 0; mi < 2; mi++) {
            int mb = mw * 32 + mi * 16;
            a[mi][0] = As[(mb + g) * HST + 8 * c + tg];
            a[mi][1] = As[(mb + g + 8) * HST + 8 * c + tg];
            a[mi][2] = As[(mb + g) * HST + 8 * c + tg + 4];
            a[mi][3] = As[(mb + g + 8) * HST + 8 * c + tg + 4];
        }
#pragma unroll
        for (int ni = 0; ni < NT; ni++) {
            int nb = nw * 56 + ni * 8 + g;
            b[ni][0] = Bs[nb * HST + 8 * c + tg];
            b[ni][1] = Bs[nb * HST + 8 * c + tg + 4];
        }
#pragma unroll
        for (int mi = 0; mi < 2; mi++)
#pragma unroll
            for (int ni = 0; ni < NT; ni++)
                mma16(acc[mi][ni], a[mi][0], a[mi][1], a[mi][2], a[mi][3],
                      b[ni][0], b[ni][1]);
    }
}

__global__ void __launch_bounds__(512, 1) accum_512(const float* __restrict__ outW,
                                                    const float* __restrict__ outb,
                                                    float* __restrict__ out) {
    extern __shared__ uint32_t sm[];
    uint32_t* A0 = sm;                        /* 256*HST words */
    uint32_t* A1 = A0 + 256 * HST;
    uint32_t* B0 = A1 + 256 * HST;            /* 104*HST words */
    uint32_t* B1 = B0 + N_PAD * HST;

    const int tid = threadIdx.x;
    const int wid = tid >> 5, lane = tid & 31;
    const int g = lane >> 2, tg = lane & 3;
    const int mw = wid & 7, nw = wid >> 3;
    const int slice = blockIdx.x;
    const int t0 = (slice * NTREE) / NSLICE;
    const int t1 = ((slice + 1) * NTREE) / NSLICE;

    const int b_local = tid >> 1;
    const int lh = tid & 1;

    float acc[2][7][4];
#pragma unroll
    for (int mi = 0; mi < 2; mi++)
#pragma unroll
        for (int ni = 0; ni < 7; ni++)
#pragma unroll
            for (int q = 0; q < 4; q++) acc[mi][ni][q] = 0.f;

    Pref cur, nxt;
    load_pref(cur, t0, outW, tid, b_local);

    int t = t0;
    while (t < t1) {
        /* --- even step: consume cur, prefetch into nxt --- */
        {
            const int buf = (t - t0) & 1;
            store_stage(cur, buf ? A1 : A0, buf ? B1 : B0, tid, b_local, lh);
            if (t + 1 < t1) load_pref(nxt, t + 1, outW, tid, b_local);
            __syncthreads();
            const uint32_t* As = buf ? A1 : A0;
            const uint32_t* Bs = buf ? B1 : B0;
            if (nw == 0) mma_trees<7>(acc, As, Bs, mw, nw, g, tg);
            else         mma_trees<6>(acc, As, Bs, mw, nw, g, tg);
        }
        if (++t >= t1) break;
        /* --- odd step: consume nxt, prefetch into cur --- */
        {
            const int buf = (t - t0) & 1;
            store_stage(nxt, buf ? A1 : A0, buf ? B1 : B0, tid, b_local, lh);
            if (t + 1 < t1) load_pref(cur, t + 1, outW, tid, b_local);
            __syncthreads();
            const uint32_t* As = buf ? A1 : A0;
            const uint32_t* Bs = buf ? B1 : B0;
            if (nw == 0) mma_trees<7>(acc, As, Bs, mw, nw, g, tg);
            else         mma_trees<6>(acc, As, Bs, mw, nw, g, tg);
        }
        ++t;
    }

    /* epilogue: atomicAdd (undo x512 W scale); CTA 0 also adds the bias */
    const int ntiles = nw ? 6 : 7;
    const bool addb = (blockIdx.x == 0);
#pragma unroll
    for (int mi = 0; mi < 2; mi++) {
        int row = mw * 32 + mi * 16 + g;
        float* op0 = out + (size_t)row * C_SZ;
        float* op1 = out + (size_t)(row + 8) * C_SZ;
#pragma unroll
        for (int ni = 0; ni < 7; ni++) {
            if (ni >= ntiles) break;
            int col = nw * 56 + ni * 8 + tg * 2;
            if (col < C_SZ) {
                float bb = addb ? outb[col] : 0.f;
                atomicAdd(op0 + col, acc[mi][ni][0] * W_INV + bb);
                atomicAdd(op1 + col, acc[mi][ni][2] * W_INV + bb);
            }
            if (col + 1 < C_SZ) {
                float bb = addb ? outb[col + 1] : 0.f;
                atomicAdd(op0 + col + 1, acc[mi][ni][1] * W_INV + bb);
                atomicAdd(op1 + col + 1, acc[mi][ni][3] * W_INV + bb);
            }
        }
    }
}

extern "C" void kernel_launch(void* const* d_in, const int* in_sizes, int n_in,
                              void* d_out, int out_size) {
    const float* x    = (const float*)d_in[0];
    const float* selW = (const float*)d_in[1];
    const float* selb = (const float*)d_in[2];
    const float* outW = (const float*)d_in[3];
    const float* outb = (const float*)d_in[4];
    float* out = (float*)d_out;

    cudaMemsetAsync(out, 0, (size_t)out_size * sizeof(float));

    size_t sel_smem = (size_t)(128 + 64) * SST * 4;                  /* 52224 B */
    cudaFuncSetAttribute(sel_fp16, cudaFuncAttributeMaxDynamicSharedMemorySize, (int)sel_smem);
    dim3 g1(384, 4);
    sel_fp16<<<g1, 256, sel_smem>>>(x, selW, selb);

    size_t acc_smem = (size_t)(2 * 256 + 2 * N_PAD) * HST * 4;       /* 103680 B */
    cudaFuncSetAttribute(accum_512, cudaFuncAttributeMaxDynamicSharedMemorySize, (int)acc_smem);
    accum_512<<<NSLICE, 512, acc_smem>>>(outW, outb, out);
}